// round 14
// baseline (speedup 1.0000x reference)
#include <cuda_runtime.h>
#include <cuda_fp16.h>
#include <cstdint>
#include <cstddef>

#define BB 16
#define LTEXT 128
#define LVIS 4096
#define DD 1024
#define HH 16
#define HD 64

// ---------------- scratch (fp16 interchange) --------------------------------------
__device__ __align__(256) __half g_A[(size_t)BB * LVIS * DD];   // hidden fp16 134MB
__device__ __align__(256) __half g_T[BB * LTEXT * DD];          // text fp16 4MB
__device__ __align__(256) __half g_W[4 * DD * DD];              // W^T (N,K) fp16 8MB
__device__ __align__(256) __half g_Q[BB * LTEXT * DD];          // Q (scaled)
__device__ __align__(256) __half g_K[(size_t)BB * LVIS * DD];   // K, later AO
__device__ __align__(256) __half g_V[(size_t)BB * LVIS * DD];   // V row-major
__device__ __align__(256) __half g_TGV[BB * HH * LTEXT * HD];   // TGV row-major
__device__ __align__(256) float g_M[BB * HH * LTEXT];
__device__ __align__(256) float g_L[BB * HH * LTEXT];

// ---------------- helpers --------------------------------------------------------
__device__ __forceinline__ uint32_t smem_u32(const void* p) {
    uint32_t a;
    asm("{ .reg .u64 t; cvta.to.shared.u64 t, %1; cvt.u32.u64 %0, t; }" : "=r"(a) : "l"(p));
    return a;
}
__device__ __forceinline__ void ldsm4(uint32_t* r, uint32_t addr) {
    asm volatile("ldmatrix.sync.aligned.m8n8.x4.shared.b16 {%0,%1,%2,%3}, [%4];"
                 : "=r"(r[0]), "=r"(r[1]), "=r"(r[2]), "=r"(r[3]) : "r"(addr));
}
__device__ __forceinline__ void ldsm4t(uint32_t* r, uint32_t addr) {
    asm volatile("ldmatrix.sync.aligned.m8n8.x4.trans.shared.b16 {%0,%1,%2,%3}, [%4];"
                 : "=r"(r[0]), "=r"(r[1]), "=r"(r[2]), "=r"(r[3]) : "r"(addr));
}
__device__ __forceinline__ void mma_h(float* d, const uint32_t* a, const uint32_t* b) {
    asm volatile("mma.sync.aligned.m16n8k16.row.col.f32.f16.f16.f32 "
                 "{%0,%1,%2,%3}, {%4,%5,%6,%7}, {%8,%9}, {%0,%1,%2,%3};"
                 : "+f"(d[0]), "+f"(d[1]), "+f"(d[2]), "+f"(d[3])
                 : "r"(a[0]), "r"(a[1]), "r"(a[2]), "r"(a[3]), "r"(b[0]), "r"(b[1]));
}
// fp16-accumulate variant (rate probe)
__device__ __forceinline__ void mma_hh(uint32_t* d, const uint32_t* a, const uint32_t* b) {
    asm volatile("mma.sync.aligned.m16n8k16.row.col.f16.f16.f16.f16 "
                 "{%0,%1}, {%2,%3,%4,%5}, {%6,%7}, {%0,%1};"
                 : "+r"(d[0]), "+r"(d[1])
                 : "r"(a[0]), "r"(a[1]), "r"(a[2]), "r"(a[3]), "r"(b[0]), "r"(b[1]));
}
__device__ __forceinline__ void cp_async16(uint32_t dst, const void* src) {
    asm volatile("cp.async.cg.shared.global [%0], [%1], 16;" :: "r"(dst), "l"(src));
}
#define CP_COMMIT() asm volatile("cp.async.commit_group;" ::: "memory")
#define CP_WAIT0() asm volatile("cp.async.wait_group 0;" ::: "memory")
#define CP_WAIT1() asm volatile("cp.async.wait_group 1;" ::: "memory")
#define CP_WAIT2() asm volatile("cp.async.wait_group 2;" ::: "memory")

__device__ __forceinline__ uint32_t packh(float a, float b) {
    __half2 h = __floats2half2_rn(a, b);
    return *(uint32_t*)&h;
}

// ---------------- conversion kernels ---------------------------------------------
__global__ void convert_half(const float* __restrict__ src, int dst_sel, size_t n4)
{
    __half* dst = dst_sel ? g_A : g_T;
    size_t stride = (size_t)gridDim.x * blockDim.x;
    for (size_t i = (size_t)blockIdx.x * blockDim.x + threadIdx.x; i < n4; i += stride) {
        float4 v = ((const float4*)src)[i];
        uint2 p = {packh(v.x, v.y), packh(v.z, v.w)};
        ((uint2*)dst)[i] = p;
    }
}

// W[K,N] fp32 -> W^T[N,K] fp16, all 4 weights in one launch (blockIdx.z = widx)
__global__ void convert_wt(const float* __restrict__ W0, const float* __restrict__ W1,
                           const float* __restrict__ W2, const float* __restrict__ W3)
{
    __shared__ float t[32][33];
    const int widx = blockIdx.z;
    const float* W = (widx == 0) ? W0 : (widx == 1) ? W1 : (widx == 2) ? W2 : W3;
    int tx = threadIdx.x, ty = threadIdx.y;   // (32,8)
    int n = blockIdx.x * 32 + tx;
    int k0 = blockIdx.y * 32;
#pragma unroll
    for (int j = 0; j < 32; j += 8)
        t[ty + j][tx] = W[(size_t)(k0 + ty + j) * DD + n];
    __syncthreads();
    __half* wt = g_W + (size_t)widx * DD * DD;
    int k = k0 + tx;
    int nn0 = blockIdx.x * 32;
#pragma unroll
    for (int j = 0; j < 32; j += 8)
        wt[(size_t)(nn0 + ty + j) * DD + k] = __float2half(t[tx][ty + j]);
}

// ---------------- fp16 GEMM, 4-stage cp.async pipeline ----------------------------
// C[M,1024] = alpha*(A@W^T + bias). 128x128 tile, BK=32, 8 warps (2m x 4n).
// a_sel: 0 = text, 1 = hidden, 2 = AO (g_K). c_mode: 0 = fp32 Cx, 1 = Q, 2 = K, 3 = V.
// HACC: 1 = fp16 accumulate with fp32 promotion every 2 k-steps (K=64 window).
#define APAD 40
#define TILE_B (128 * APAD * 2)      // 10240 B (one operand tile)
#define STAGE_B (2 * TILE_B)         // 20480 B (A+B)
#define G_STAGES 4
#define G_SMEM (G_STAGES * STAGE_B)  // 81920 B

template <int HACC>
__global__ void __launch_bounds__(256)
gemm_h(int a_sel, int w_idx, const float* __restrict__ bias, float* __restrict__ Cx,
       int c_mode, float alpha)
{
    extern __shared__ __align__(256) char smem[];
    const uint32_t sb = smem_u32(smem);
    const int tid = threadIdx.x;
    const int wid = tid >> 5, lane = tid & 31;
    const int warp_m = wid & 1, warp_n = wid >> 1;

    const __half* A = (a_sel == 0) ? g_T : (a_sel == 1) ? g_A : g_K;
    const __half* B = g_W + (size_t)w_idx * DD * DD;

    const int n0 = blockIdx.x * 128;
    const size_t m0 = (size_t)blockIdx.y * 128;

    float acc[4][4][4] = {};
    uint32_t hacc[4][4][2];
    if (HACC) {
#pragma unroll
        for (int mi = 0; mi < 4; mi++)
#pragma unroll
            for (int ni = 0; ni < 4; ni++) { hacc[mi][ni][0] = 0; hacc[mi][ni][1] = 0; }
    }

    auto issue = [&](int kt) {
        const int k0 = kt * 32;
        const uint32_t sdst = sb + (kt & 3) * STAGE_B;
#pragma unroll
        for (int i = 0; i < 4; i++) {
            int q = tid + i * 256;
            int tile = q >> 9, rem = q & 511, r = rem >> 2, seg = rem & 3;
            const __half* src = tile ? B + (size_t)(n0 + r) * DD + k0 + seg * 8
                                     : A + (m0 + r) * DD + k0 + seg * 8;
            cp_async16(sdst + tile * TILE_B + (r * APAD + seg * 8) * 2, src);
        }
        CP_COMMIT();
    };

    issue(0); issue(1); issue(2);
    for (int kt = 0; kt < 32; kt++) {
        if (kt < 30) CP_WAIT2();
        else if (kt == 30) CP_WAIT1();
        else CP_WAIT0();
        __syncthreads();
        if (kt + 3 < 32) issue(kt + 3);

        const uint32_t so = sb + (kt & 3) * STAGE_B;
        const int lm = lane & 7, quad = lane >> 3;
#pragma unroll
        for (int ks = 0; ks < 2; ks++) {
            uint32_t af[4][4], bf[2][4];
            const int arow = warp_m * 64 + (lane & 15);
            const int acol = ks * 16 + (lane >> 4) * 8;
#pragma unroll
            for (int mi = 0; mi < 4; mi++)
                ldsm4(af[mi], so + ((arow + mi * 16) * APAD + acol) * 2);
            const int brow = warp_n * 32 + ((quad & 2) ? 8 : 0) + lm;
            const int bcol = ks * 16 + (quad & 1) * 8;
#pragma unroll
            for (int np = 0; np < 2; np++)
                ldsm4(bf[np], so + TILE_B + ((brow + np * 16) * APAD + bcol) * 2);
#pragma unroll
            for (int mi = 0; mi < 4; mi++)
#pragma unroll
                for (int ni = 0; ni < 4; ni++) {
                    if (HACC) mma_hh(hacc[mi][ni], af[mi], &bf[ni >> 1][(ni & 1) * 2]);
                    else mma_h(acc[mi][ni], af[mi], &bf[ni >> 1][(ni & 1) * 2]);
                }
        }
        // promote fp16 partials to fp32 every 2 k-steps (K=64 window)
        if (HACC && (kt & 1)) {
#pragma unroll
            for (int mi = 0; mi < 4; mi++)
#pragma unroll
                for (int ni = 0; ni < 4; ni++) {
                    float2 f0 = __half22float2(*(__half2*)&hacc[mi][ni][0]);
                    float2 f1 = __half22float2(*(__half2*)&hacc[mi][ni][1]);
                    acc[mi][ni][0] += f0.x; acc[mi][ni][1] += f0.y;
                    acc[mi][ni][2] += f1.x; acc[mi][ni][3] += f1.y;
                    hacc[mi][ni][0] = 0; hacc[mi][ni][1] = 0;
                }
        }
    }

    // epilogue
    __half* Ch = (c_mode == 1) ? g_Q : (c_mode == 2) ? g_K : g_V;
#pragma unroll
    for (int ni = 0; ni < 4; ni++) {
        const int col = n0 + warp_n * 32 + ni * 8 + (lane & 3) * 2;
        const float b0 = bias[col], b1 = bias[col + 1];
#pragma unroll
        for (int mi = 0; mi < 4; mi++) {
            const size_t r0 = m0 + warp_m * 64 + mi * 16 + (lane >> 2);
            float v00 = alpha * (acc[mi][ni][0] + b0);
            float v01 = alpha * (acc[mi][ni][1] + b1);
            float v10 = alpha * (acc[mi][ni][2] + b0);
            float v11 = alpha * (acc[mi][ni][3] + b1);
            if (c_mode == 0) {
                *(float2*)&Cx[r0 * DD + col] = {v00, v01};
                *(float2*)&Cx[(r0 + 8) * DD + col] = {v10, v11};
            } else {
                *(uint32_t*)&Ch[r0 * DD + col] = packh(v00, v01);
                *(uint32_t*)&Ch[(r0 + 8) * DD + col] = packh(v10, v11);
            }
        }
    }
}

// ---------------- attention pass 1 (fp16 flash, double-buffered KV) ---------------
#define AT_STRIDE 72
#define AT_TILE (128 * AT_STRIDE * 2)   // 18432 B
#define KV_SET (2 * AT_TILE)            // K+V set
#define P1_SMEM (AT_TILE + 2 * KV_SET)  // Q + 2 KV sets = 92160 B

__global__ void __launch_bounds__(256, 2)
attn1_h()
{
    extern __shared__ __align__(256) char smem[];
    const uint32_t sb = smem_u32(smem);
    const int tid = threadIdx.x;
    const int wid = tid >> 5, lane = tid & 31;
    const int bh = blockIdx.x, b = bh >> 4, h = bh & 15;

    const __half* Qg = g_Q + (size_t)(b * LTEXT) * DD + h * HD;

#pragma unroll
    for (int i = 0; i < 4; i++) {
        int q = tid + i * 256;
        int r = q >> 3, s = q & 7;
        cp_async16(sb + r * (AT_STRIDE * 2) + s * 16, Qg + (size_t)r * DD + s * 8);
    }

    auto issue_kv = [&](int cc) {
        const size_t row0 = (size_t)b * LVIS + cc * 128;
        const uint32_t base = sb + AT_TILE + (cc & 1) * KV_SET;
#pragma unroll
        for (int i = 0; i < 8; i++) {
            int q = tid + i * 256;
            int tile = q >> 10, rem = q & 1023, r = rem >> 3, s = rem & 7;
            const __half* src = tile ? g_V + (row0 + r) * DD + h * HD + s * 8
                                     : g_K + (row0 + r) * DD + h * HD + s * 8;
            cp_async16(base + tile * AT_TILE + r * (AT_STRIDE * 2) + s * 16, src);
        }
    };

    issue_kv(0);
    CP_COMMIT();
    CP_WAIT0();
    __syncthreads();

    uint32_t qf[4][4];
#pragma unroll
    for (int ks = 0; ks < 4; ks++) {
        uint32_t off = ((wid * 16 + (lane & 15)) * AT_STRIDE + ks * 16 + (lane >> 4) * 8) * 2;
        ldsm4(qf[ks], sb + off);
    }

    issue_kv(1);
    CP_COMMIT();

    float m0 = -1e30f, m1 = -1e30f, l0 = 0.f, l1 = 0.f;
    float O[8][4] = {};
    const int lm = lane & 7, quad = lane >> 3;

    for (int cc = 0; cc < LVIS / 128; cc++) {
        if (cc > 0) {
            if (cc < 31) CP_WAIT1(); else CP_WAIT0();
            __syncthreads();
        }
        const uint32_t kvb = sb + AT_TILE + (cc & 1) * KV_SET;

        float S[16][4] = {};
#pragma unroll
        for (int nb = 0; nb < 4; nb++) {
#pragma unroll
            for (int ks = 0; ks < 4; ks++) {
                uint32_t bk[2][4];
                const int brow = nb * 32 + ((quad & 2) ? 8 : 0) + lm;
                const int bcol = ks * 16 + (quad & 1) * 8;
#pragma unroll
                for (int np = 0; np < 2; np++)
                    ldsm4(bk[np], kvb + ((brow + np * 16) * AT_STRIDE + bcol) * 2);
#pragma unroll
                for (int ni = 0; ni < 4; ni++)
                    mma_h(S[nb * 4 + ni], qf[ks], &bk[ni >> 1][(ni & 1) * 2]);
            }
        }

        float mx0 = S[0][0], mx1 = S[0][2];
#pragma unroll
        for (int nt = 0; nt < 16; nt++) {
            mx0 = fmaxf(mx0, fmaxf(S[nt][0], S[nt][1]));
            mx1 = fmaxf(mx1, fmaxf(S[nt][2], S[nt][3]));
        }
        mx0 = fmaxf(mx0, __shfl_xor_sync(0xffffffffu, mx0, 1));
        mx0 = fmaxf(mx0, __shfl_xor_sync(0xffffffffu, mx0, 2));
        mx1 = fmaxf(mx1, __shfl_xor_sync(0xffffffffu, mx1, 1));
        mx1 = fmaxf(mx1, __shfl_xor_sync(0xffffffffu, mx1, 2));
        float mn0 = fmaxf(m0, mx0), mn1 = fmaxf(m1, mx1);
        float corr0 = __expf(m0 - mn0), corr1 = __expf(m1 - mn1);
        m0 = mn0; m1 = mn1;
        float rs0 = 0.f, rs1 = 0.f;
#pragma unroll
        for (int nt = 0; nt < 16; nt++) {
            S[nt][0] = __expf(S[nt][0] - m0); rs0 += S[nt][0];
            S[nt][1] = __expf(S[nt][1] - m0); rs0 += S[nt][1];
            S[nt][2] = __expf(S[nt][2] - m1); rs1 += S[nt][2];
            S[nt][3] = __expf(S[nt][3] - m1); rs1 += S[nt][3];
        }
        rs0 += __shfl_xor_sync(0xffffffffu, rs0, 1);
        rs0 += __shfl_xor_sync(0xffffffffu, rs0, 2);
        rs1 += __shfl_xor_sync(0xffffffffu, rs1, 1);
        rs1 += __shfl_xor_sync(0xffffffffu, rs1, 2);
        l0 = l0 * corr0 + rs0;
        l1 = l1 * corr1 + rs1;
#pragma unroll
        for (int nt = 0; nt < 8; nt++) {
            O[nt][0] *= corr0; O[nt][1] *= corr0;
            O[nt][2] *= corr1; O[nt][3] *= corr1;
        }

#pragma unroll
        for (int ks2 = 0; ks2 < 8; ks2++) {
            uint32_t pa[4] = {packh(S[2 * ks2][0], S[2 * ks2][1]),
                              packh(S[2 * ks2][2], S[2 * ks2][3]),
                              packh(S[2 * ks2 + 1][0], S[2 * ks2 + 1][1]),
                              packh(S[2 * ks2 + 1][2], S[2 * ks2 + 1][3])};
            const int vrow = ks2 * 16 + ((lane >> 3) & 1) * 8 + (lane & 7);
#pragma unroll
            for (int nv = 0; nv < 4; nv++) {
                const int vcol = nv * 16 + (lane >> 4) * 8;
                uint32_t bv[4];
                ldsm4t(bv, kvb + AT_TILE + (vrow * AT_STRIDE + vcol) * 2);
                mma_h(O[nv * 2], pa, &bv[0]);
                mma_h(O[nv * 2 + 1], pa, &bv[2]);
            }
        }

        if (cc + 2 < LVIS / 128) {
            __syncthreads();
            issue_kv(cc + 2);
            CP_COMMIT();
        }
    }

    const float inv0 = 1.f / l0, inv1 = 1.f / l1;
    const int r = lane >> 2, q = lane & 3;
    const int t0 = wid * 16 + r, t1 = t0 + 8;
#pragma unroll
    for (int nt = 0; nt < 8; nt++) {
        int col = nt * 8 + q * 2;
        *(uint32_t*)&g_TGV[((size_t)bh * 128 + t0) * 64 + col] =
            packh(O[nt][0] * inv0, O[nt][1] * inv0);
        *(uint32_t*)&g_TGV[((size_t)bh * 128 + t1) * 64 + col] =
            packh(O[nt][2] * inv1, O[nt][3] * inv1);
    }
    if (q == 0) {
        g_M[bh * 128 + t0] = m0; g_M[bh * 128 + t1] = m1;
        g_L[bh * 128 + t0] = l0; g_L[bh * 128 + t1] = l1;
    }
}

// ---------------- attention pass 2 (fp16) -----------------------------------------
#define P2_SMEM (3 * AT_TILE + 1024)

__global__ void __launch_bounds__(256, 2)
attn2_h()
{
    extern __shared__ __align__(256) char smem[];
    const uint32_t sb = smem_u32(smem);
    float* m_s = (float*)(smem + 3 * AT_TILE);
    float* rl_s = m_s + 128;
    const int tid = threadIdx.x;
    const int wid = tid >> 5, lane = tid & 31;
    const int cc = blockIdx.x, bh = blockIdx.y, b = bh >> 4, h = bh & 15;
    const size_t row0 = (size_t)b * LVIS + cc * 128;

#pragma unroll
    for (int i = 0; i < 12; i++) {
        int q = tid + i * 256;
        int tile = q >> 10, rem = q & 1023, r = rem >> 3, s = rem & 7;
        const __half* src;
        if (tile == 0)      src = g_Q + (size_t)(b * LTEXT + r) * DD + h * HD + s * 8;
        else if (tile == 1) src = g_K + (row0 + r) * DD + h * HD + s * 8;
        else                src = g_TGV + ((size_t)bh * 128 + r) * 64 + s * 8;
        cp_async16(sb + tile * AT_TILE + r * (AT_STRIDE * 2) + s * 16, src);
    }
    CP_COMMIT();
    if (tid < 128) {
        m_s[tid] = g_M[bh * 128 + tid];
        rl_s[tid] = 1.f / g_L[bh * 128 + tid];
    }
    CP_WAIT0();
    __syncthreads();

    uint32_t kf[4][4];
#pragma unroll
    for (int ks = 0; ks < 4; ks++) {
        uint32_t off = ((wid * 16 + (lane & 15)) * AT_STRIDE + ks * 16 + (lane >> 4) * 8) * 2;
        ldsm4(kf[ks], sb + AT_TILE + off);
    }

    float S[16][4] = {};
    const int lm = lane & 7, quad = lane >> 3;
#pragma unroll
    for (int nb = 0; nb < 4; nb++) {
#pragma unroll
        for (int ks = 0; ks < 4; ks++) {
            uint32_t bq[2][4];
            const int brow = nb * 32 + ((quad & 2) ? 8 : 0) + lm;
            const int bcol = ks * 16 + (quad & 1) * 8;
#pragma unroll
            for (int np = 0; np < 2; np++)
                ldsm4(bq[np], sb + ((brow + np * 16) * AT_STRIDE + bcol) * 2);
#pragma unroll
            for (int ni = 0; ni < 4; ni++)
                mma_h(S[nb * 4 + ni], kf[ks], &bq[ni >> 1][(ni & 1) * 2]);
        }
    }

    const int q = lane & 3;
#pragma unroll
    for (int nt = 0; nt < 16; nt++) {
        int c0 = nt * 8 + q * 2;
        S[nt][0] = __expf(S[nt][0] - m_s[c0]) * rl_s[c0];
        S[nt][1] = __expf(S[nt][1] - m_s[c0 + 1]) * rl_s[c0 + 1];
        S[nt][2] = __expf(S[nt][2] - m_s[c0]) * rl_s[c0];
        S[nt][3] = __expf(S[nt][3] - m_s[c0 + 1]) * rl_s[c0 + 1];
    }

    float O[8][4] = {};
#pragma unroll
    for (int ks2 = 0; ks2 < 8; ks2++) {
        uint32_t pa[4] = {packh(S[2 * ks2][0], S[2 * ks2][1]),
                          packh(S[2 * ks2][2], S[2 * ks2][3]),
                          packh(S[2 * ks2 + 1][0], S[2 * ks2 + 1][1]),
                          packh(S[2 * ks2 + 1][2], S[2 * ks2 + 1][3])};
        const int vrow = ks2 * 16 + ((lane >> 3) & 1) * 8 + (lane & 7);
#pragma unroll
        for (int nv = 0; nv < 4; nv++) {
            const int vcol = nv * 16 + (lane >> 4) * 8;
            uint32_t bv[4];
            ldsm4t(bv, sb + 2 * AT_TILE + (vrow * AT_STRIDE + vcol) * 2);
            mma_h(O[nv * 2], pa, &bv[0]);
            mma_h(O[nv * 2 + 1], pa, &bv[2]);
        }
    }

    const int r = lane >> 2;
    const size_t s0r = row0 + wid * 16 + r;
#pragma unroll
    for (int nt = 0; nt < 8; nt++) {
        int col = h * HD + nt * 8 + q * 2;
        *(uint32_t*)&g_K[s0r * DD + col] = packh(O[nt][0], O[nt][1]);
        *(uint32_t*)&g_K[(s0r + 8) * DD + col] = packh(O[nt][2], O[nt][3]);
    }
}

// ---------------- launch ----------------------------------------------------------
extern "C" void kernel_launch(void* const* d_in, const int* in_sizes, int n_in,
                              void* d_out, int out_size)
{
    const float* hidden = nullptr;
    const float* text = nullptr;
    const float* Ws[4] = {nullptr, nullptr, nullptr, nullptr};
    const float* bs[4] = {nullptr, nullptr, nullptr, nullptr};
    int nw = 0, nb = 0;
    for (int i = 0; i < n_in; i++) {
        int sz = in_sizes[i];
        const float* p = (const float*)d_in[i];
        if (sz == BB * LVIS * DD) { if (!hidden) hidden = p; }
        else if (sz == LTEXT * BB * DD) { if (!text) text = p; }
        else if (sz == DD * DD) { if (nw < 4) Ws[nw++] = p; }
        else if (sz == DD) { if (nb < 4) bs[nb++] = p; }
    }
    if (!hidden) hidden = (const float*)d_in[0];
    if (!text) text = (const float*)d_in[1];
    if (nw < 4) { Ws[0]=(const float*)d_in[2]; Ws[1]=(const float*)d_in[4];
                  Ws[2]=(const float*)d_in[6]; Ws[3]=(const float*)d_in[8]; }
    if (nb < 4) { bs[0]=(const float*)d_in[3]; bs[1]=(const float*)d_in[5];
                  bs[2]=(const float*)d_in[7]; bs[3]=(const float*)d_in[9]; }
    float* out = (float*)d_out;

    cudaFuncSetAttribute(gemm_h<0>, cudaFuncAttributeMaxDynamicSharedMemorySize, G_SMEM);
    cudaFuncSetAttribute(gemm_h<1>, cudaFuncAttributeMaxDynamicSharedMemorySize, G_SMEM);
    cudaFuncSetAttribute(attn1_h, cudaFuncAttributeMaxDynamicSharedMemorySize, P1_SMEM);
    cudaFuncSetAttribute(attn2_h, cudaFuncAttributeMaxDynamicSharedMemorySize, P2_SMEM);

    convert_wt<<<dim3(32, 32, 4), dim3(32, 8)>>>(Ws[0], Ws[1], Ws[2], Ws[3]);
    convert_half<<<2048, 256>>>(text, 0, (size_t)LTEXT * BB * DD / 4);
    convert_half<<<8192, 256>>>(hidden, 1, (size_t)BB * LVIS * DD / 4);

    gemm_h<0><<<dim3(8, 16), 256, G_SMEM>>>(0, 0, bs[0], nullptr, 1, 0.125f);  // Q
    gemm_h<1><<<dim3(8, 512), 256, G_SMEM>>>(1, 1, bs[1], nullptr, 2, 1.f);    // K (probe)
    gemm_h<1><<<dim3(8, 512), 256, G_SMEM>>>(1, 2, bs[2], nullptr, 3, 1.f);    // V (probe)

    attn1_h<<<BB * HH, 256, P1_SMEM>>>();
    attn2_h<<<dim3(LVIS / 128, BB * HH), 256, P2_SMEM>>>();

    gemm_h<0><<<dim3(8, 512), 256, G_SMEM>>>(2, 3, bs[3], out, 0, 1.f);        // O
}

// round 16
// speedup vs baseline: 1.1189x; 1.1189x over previous
#include <cuda_runtime.h>
#include <cuda_fp16.h>
#include <cstdint>
#include <cstddef>

#define BB 16
#define LTEXT 128
#define LVIS 4096
#define DD 1024
#define HH 16
#define HD 64

// ---------------- scratch (fp16 interchange) --------------------------------------
__device__ __align__(256) __half g_A[(size_t)BB * LVIS * DD];   // hidden fp16 134MB
__device__ __align__(256) __half g_T[BB * LTEXT * DD];          // text fp16 4MB
__device__ __align__(256) __half g_W[4 * DD * DD];              // W^T (N,K) fp16 8MB
__device__ __align__(256) __half g_Q[BB * LTEXT * DD];          // Q (scaled)
__device__ __align__(256) __half g_K[(size_t)BB * LVIS * DD];   // K, later AO
__device__ __align__(256) __half g_V[(size_t)BB * LVIS * DD];   // V row-major
__device__ __align__(256) __half g_TGV[BB * HH * LTEXT * HD];   // TGV row-major
__device__ __align__(256) float g_M[BB * HH * LTEXT];
__device__ __align__(256) float g_L[BB * HH * LTEXT];

// ---------------- helpers --------------------------------------------------------
__device__ __forceinline__ uint32_t smem_u32(const void* p) {
    uint32_t a;
    asm("{ .reg .u64 t; cvta.to.shared.u64 t, %1; cvt.u32.u64 %0, t; }" : "=r"(a) : "l"(p));
    return a;
}
__device__ __forceinline__ void ldsm4(uint32_t* r, uint32_t addr) {
    asm volatile("ldmatrix.sync.aligned.m8n8.x4.shared.b16 {%0,%1,%2,%3}, [%4];"
                 : "=r"(r[0]), "=r"(r[1]), "=r"(r[2]), "=r"(r[3]) : "r"(addr));
}
__device__ __forceinline__ void ldsm4t(uint32_t* r, uint32_t addr) {
    asm volatile("ldmatrix.sync.aligned.m8n8.x4.trans.shared.b16 {%0,%1,%2,%3}, [%4];"
                 : "=r"(r[0]), "=r"(r[1]), "=r"(r[2]), "=r"(r[3]) : "r"(addr));
}
__device__ __forceinline__ void mma_h(float* d, const uint32_t* a, const uint32_t* b) {
    asm volatile("mma.sync.aligned.m16n8k16.row.col.f32.f16.f16.f32 "
                 "{%0,%1,%2,%3}, {%4,%5,%6,%7}, {%8,%9}, {%0,%1,%2,%3};"
                 : "+f"(d[0]), "+f"(d[1]), "+f"(d[2]), "+f"(d[3])
                 : "r"(a[0]), "r"(a[1]), "r"(a[2]), "r"(a[3]), "r"(b[0]), "r"(b[1]));
}
__device__ __forceinline__ void cp_async16(uint32_t dst, const void* src) {
    asm volatile("cp.async.cg.shared.global [%0], [%1], 16;" :: "r"(dst), "l"(src));
}
#define CP_COMMIT() asm volatile("cp.async.commit_group;" ::: "memory")
#define CP_WAIT0() asm volatile("cp.async.wait_group 0;" ::: "memory")
#define CP_WAIT1() asm volatile("cp.async.wait_group 1;" ::: "memory")
#define CP_WAIT2() asm volatile("cp.async.wait_group 2;" ::: "memory")

__device__ __forceinline__ uint32_t packh(float a, float b) {
    __half2 h = __floats2half2_rn(a, b);
    return *(uint32_t*)&h;
}

// ---------------- conversion kernels ---------------------------------------------
// One launch converts BOTH text (-> g_T) and hidden (-> g_A).
__global__ void convert_half2(const float* __restrict__ text,
                              const float* __restrict__ hidden)
{
    const size_t n4t = (size_t)LTEXT * BB * DD / 4;          // 524288
    const size_t n4h = (size_t)BB * LVIS * DD / 4;           // 16777216
    size_t stride = (size_t)gridDim.x * blockDim.x;
    for (size_t i = (size_t)blockIdx.x * blockDim.x + threadIdx.x; i < n4t + n4h;
         i += stride) {
        const float* src;
        __half* dst;
        size_t j;
        if (i < n4t) { src = text; dst = g_T; j = i; }
        else { src = hidden; dst = g_A; j = i - n4t; }
        float4 v = ((const float4*)src)[j];
        uint2 p = {packh(v.x, v.y), packh(v.z, v.w)};
        ((uint2*)dst)[j] = p;
    }
}

// W[K,N] fp32 -> W^T[N,K] fp16, all 4 weights in one launch (blockIdx.z = widx)
__global__ void convert_wt(const float* __restrict__ W0, const float* __restrict__ W1,
                           const float* __restrict__ W2, const float* __restrict__ W3)
{
    __shared__ float t[32][33];
    const int widx = blockIdx.z;
    const float* W = (widx == 0) ? W0 : (widx == 1) ? W1 : (widx == 2) ? W2 : W3;
    int tx = threadIdx.x, ty = threadIdx.y;   // (32,8)
    int n = blockIdx.x * 32 + tx;
    int k0 = blockIdx.y * 32;
#pragma unroll
    for (int j = 0; j < 32; j += 8)
        t[ty + j][tx] = W[(size_t)(k0 + ty + j) * DD + n];
    __syncthreads();
    __half* wt = g_W + (size_t)widx * DD * DD;
    int k = k0 + tx;
    int nn0 = blockIdx.x * 32;
#pragma unroll
    for (int j = 0; j < 32; j += 8)
        wt[(size_t)(nn0 + ty + j) * DD + k] = __float2half(t[tx][ty + j]);
}

// ---------------- fp16 GEMM, 4-stage cp.async pipeline ----------------------------
// C[M,1024] = alpha*(A@W^T + bias). 128x128 tile, BK=32, 8 warps (2m x 4n).
// a_sel: 0 = text, 1 = hidden, 2 = AO (g_K). c_mode: 0 = fp32 Cx, 1 = Q, 2 = K, 3 = V.
#define APAD 40
#define TILE_B (128 * APAD * 2)      // 10240 B (one operand tile)
#define STAGE_B (2 * TILE_B)         // 20480 B (A+B)
#define G_STAGES 4
#define G_SMEM (G_STAGES * STAGE_B)  // 81920 B

__global__ void __launch_bounds__(256, 2)
gemm_h(int a_sel, int w_idx, const float* __restrict__ bias, float* __restrict__ Cx,
       int c_mode, float alpha)
{
    extern __shared__ __align__(256) char smem[];
    const uint32_t sb = smem_u32(smem);
    const int tid = threadIdx.x;
    const int wid = tid >> 5, lane = tid & 31;
    const int warp_m = wid & 1, warp_n = wid >> 1;

    const __half* A = (a_sel == 0) ? g_T : (a_sel == 1) ? g_A : g_K;
    const __half* B = g_W + (size_t)w_idx * DD * DD;

    const int n0 = blockIdx.x * 128;
    const size_t m0 = (size_t)blockIdx.y * 128;

    float acc[4][4][4] = {};

    auto issue = [&](int kt) {
        const int k0 = kt * 32;
        const uint32_t sdst = sb + (kt & 3) * STAGE_B;
#pragma unroll
        for (int i = 0; i < 4; i++) {
            int q = tid + i * 256;
            int tile = q >> 9, rem = q & 511, r = rem >> 2, seg = rem & 3;
            const __half* src = tile ? B + (size_t)(n0 + r) * DD + k0 + seg * 8
                                     : A + (m0 + r) * DD + k0 + seg * 8;
            cp_async16(sdst + tile * TILE_B + (r * APAD + seg * 8) * 2, src);
        }
        CP_COMMIT();
    };

    issue(0); issue(1); issue(2);
    for (int kt = 0; kt < 32; kt++) {
        if (kt < 30) CP_WAIT2();
        else if (kt == 30) CP_WAIT1();
        else CP_WAIT0();
        __syncthreads();
        // refill stage (kt+3)&3 == (kt-1)&3 — consumed at iter kt-1.
        if (kt + 3 < 32) issue(kt + 3);

        const uint32_t so = sb + (kt & 3) * STAGE_B;
        const int lm = lane & 7, quad = lane >> 3;
#pragma unroll
        for (int ks = 0; ks < 2; ks++) {
            uint32_t af[4][4], bf[2][4];
            const int arow = warp_m * 64 + (lane & 15);
            const int acol = ks * 16 + (lane >> 4) * 8;
#pragma unroll
            for (int mi = 0; mi < 4; mi++)
                ldsm4(af[mi], so + ((arow + mi * 16) * APAD + acol) * 2);
            const int brow = warp_n * 32 + ((quad & 2) ? 8 : 0) + lm;
            const int bcol = ks * 16 + (quad & 1) * 8;
#pragma unroll
            for (int np = 0; np < 2; np++)
                ldsm4(bf[np], so + TILE_B + ((brow + np * 16) * APAD + bcol) * 2);
#pragma unroll
            for (int mi = 0; mi < 4; mi++)
#pragma unroll
                for (int ni = 0; ni < 4; ni++)
                    mma_h(acc[mi][ni], af[mi], &bf[ni >> 1][(ni & 1) * 2]);
        }
    }

    // epilogue
    __half* Ch = (c_mode == 1) ? g_Q : (c_mode == 2) ? g_K : g_V;
#pragma unroll
    for (int ni = 0; ni < 4; ni++) {
        const int col = n0 + warp_n * 32 + ni * 8 + (lane & 3) * 2;
        const float b0 = bias[col], b1 = bias[col + 1];
#pragma unroll
        for (int mi = 0; mi < 4; mi++) {
            const size_t r0 = m0 + warp_m * 64 + mi * 16 + (lane >> 2);
            float v00 = alpha * (acc[mi][ni][0] + b0);
            float v01 = alpha * (acc[mi][ni][1] + b1);
            float v10 = alpha * (acc[mi][ni][2] + b0);
            float v11 = alpha * (acc[mi][ni][3] + b1);
            if (c_mode == 0) {
                *(float2*)&Cx[r0 * DD + col] = {v00, v01};
                *(float2*)&Cx[(r0 + 8) * DD + col] = {v10, v11};
            } else {
                *(uint32_t*)&Ch[r0 * DD + col] = packh(v00, v01);
                *(uint32_t*)&Ch[(r0 + 8) * DD + col] = packh(v10, v11);
            }
        }
    }
}

// ---------------- attention pass 1 (fp16 flash, double-buffered KV) ---------------
#define AT_STRIDE 72
#define AT_TILE (128 * AT_STRIDE * 2)   // 18432 B
#define KV_SET (2 * AT_TILE)            // K+V set
#define P1_SMEM (AT_TILE + 2 * KV_SET)  // Q + 2 KV sets = 92160 B

__global__ void __launch_bounds__(256, 2)
attn1_h()
{
    extern __shared__ __align__(256) char smem[];
    const uint32_t sb = smem_u32(smem);
    const int tid = threadIdx.x;
    const int wid = tid >> 5, lane = tid & 31;
    const int bh = blockIdx.x, b = bh >> 4, h = bh & 15;

    const __half* Qg = g_Q + (size_t)(b * LTEXT) * DD + h * HD;

#pragma unroll
    for (int i = 0; i < 4; i++) {
        int q = tid + i * 256;
        int r = q >> 3, s = q & 7;
        cp_async16(sb + r * (AT_STRIDE * 2) + s * 16, Qg + (size_t)r * DD + s * 8);
    }

    auto issue_kv = [&](int cc) {
        const size_t row0 = (size_t)b * LVIS + cc * 128;
        const uint32_t base = sb + AT_TILE + (cc & 1) * KV_SET;
#pragma unroll
        for (int i = 0; i < 8; i++) {
            int q = tid + i * 256;
            int tile = q >> 10, rem = q & 1023, r = rem >> 3, s = rem & 7;
            const __half* src = tile ? g_V + (row0 + r) * DD + h * HD + s * 8
                                     : g_K + (row0 + r) * DD + h * HD + s * 8;
            cp_async16(base + tile * AT_TILE + r * (AT_STRIDE * 2) + s * 16, src);
        }
    };

    issue_kv(0);
    CP_COMMIT();
    CP_WAIT0();
    __syncthreads();

    uint32_t qf[4][4];
#pragma unroll
    for (int ks = 0; ks < 4; ks++) {
        uint32_t off = ((wid * 16 + (lane & 15)) * AT_STRIDE + ks * 16 + (lane >> 4) * 8) * 2;
        ldsm4(qf[ks], sb + off);
    }

    issue_kv(1);
    CP_COMMIT();

    float m0 = -1e30f, m1 = -1e30f, l0 = 0.f, l1 = 0.f;
    float O[8][4] = {};
    const int lm = lane & 7, quad = lane >> 3;

    for (int cc = 0; cc < LVIS / 128; cc++) {
        if (cc > 0) {
            if (cc < 31) CP_WAIT1(); else CP_WAIT0();
            __syncthreads();
        }
        const uint32_t kvb = sb + AT_TILE + (cc & 1) * KV_SET;

        float S[16][4] = {};
#pragma unroll
        for (int nb = 0; nb < 4; nb++) {
#pragma unroll
            for (int ks = 0; ks < 4; ks++) {
                uint32_t bk[2][4];
                const int brow = nb * 32 + ((quad & 2) ? 8 : 0) + lm;
                const int bcol = ks * 16 + (quad & 1) * 8;
#pragma unroll
                for (int np = 0; np < 2; np++)
                    ldsm4(bk[np], kvb + ((brow + np * 16) * AT_STRIDE + bcol) * 2);
#pragma unroll
                for (int ni = 0; ni < 4; ni++)
                    mma_h(S[nb * 4 + ni], qf[ks], &bk[ni >> 1][(ni & 1) * 2]);
            }
        }

        float mx0 = S[0][0], mx1 = S[0][2];
#pragma unroll
        for (int nt = 0; nt < 16; nt++) {
            mx0 = fmaxf(mx0, fmaxf(S[nt][0], S[nt][1]));
            mx1 = fmaxf(mx1, fmaxf(S[nt][2], S[nt][3]));
        }
        mx0 = fmaxf(mx0, __shfl_xor_sync(0xffffffffu, mx0, 1));
        mx0 = fmaxf(mx0, __shfl_xor_sync(0xffffffffu, mx0, 2));
        mx1 = fmaxf(mx1, __shfl_xor_sync(0xffffffffu, mx1, 1));
        mx1 = fmaxf(mx1, __shfl_xor_sync(0xffffffffu, mx1, 2));
        float mn0 = fmaxf(m0, mx0), mn1 = fmaxf(m1, mx1);
        float corr0 = __expf(m0 - mn0), corr1 = __expf(m1 - mn1);
        m0 = mn0; m1 = mn1;
        float rs0 = 0.f, rs1 = 0.f;
#pragma unroll
        for (int nt = 0; nt < 16; nt++) {
            S[nt][0] = __expf(S[nt][0] - m0); rs0 += S[nt][0];
            S[nt][1] = __expf(S[nt][1] - m0); rs0 += S[nt][1];
            S[nt][2] = __expf(S[nt][2] - m1); rs1 += S[nt][2];
            S[nt][3] = __expf(S[nt][3] - m1); rs1 += S[nt][3];
        }
        rs0 += __shfl_xor_sync(0xffffffffu, rs0, 1);
        rs0 += __shfl_xor_sync(0xffffffffu, rs0, 2);
        rs1 += __shfl_xor_sync(0xffffffffu, rs1, 1);
        rs1 += __shfl_xor_sync(0xffffffffu, rs1, 2);
        l0 = l0 * corr0 + rs0;
        l1 = l1 * corr1 + rs1;
#pragma unroll
        for (int nt = 0; nt < 8; nt++) {
            O[nt][0] *= corr0; O[nt][1] *= corr0;
            O[nt][2] *= corr1; O[nt][3] *= corr1;
        }

#pragma unroll
        for (int ks2 = 0; ks2 < 8; ks2++) {
            uint32_t pa[4] = {packh(S[2 * ks2][0], S[2 * ks2][1]),
                              packh(S[2 * ks2][2], S[2 * ks2][3]),
                              packh(S[2 * ks2 + 1][0], S[2 * ks2 + 1][1]),
                              packh(S[2 * ks2 + 1][2], S[2 * ks2 + 1][3])};
            const int vrow = ks2 * 16 + ((lane >> 3) & 1) * 8 + (lane & 7);
#pragma unroll
            for (int nv = 0; nv < 4; nv++) {
                const int vcol = nv * 16 + (lane >> 4) * 8;
                uint32_t bv[4];
                ldsm4t(bv, kvb + AT_TILE + (vrow * AT_STRIDE + vcol) * 2);
                mma_h(O[nv * 2], pa, &bv[0]);
                mma_h(O[nv * 2 + 1], pa, &bv[2]);
            }
        }

        if (cc + 2 < LVIS / 128) {
            __syncthreads();
            issue_kv(cc + 2);
            CP_COMMIT();
        }
    }

    const float inv0 = 1.f / l0, inv1 = 1.f / l1;
    const int r = lane >> 2, q = lane & 3;
    const int t0 = wid * 16 + r, t1 = t0 + 8;
#pragma unroll
    for (int nt = 0; nt < 8; nt++) {
        int col = nt * 8 + q * 2;
        *(uint32_t*)&g_TGV[((size_t)bh * 128 + t0) * 64 + col] =
            packh(O[nt][0] * inv0, O[nt][1] * inv0);
        *(uint32_t*)&g_TGV[((size_t)bh * 128 + t1) * 64 + col] =
            packh(O[nt][2] * inv1, O[nt][3] * inv1);
    }
    if (q == 0) {
        g_M[bh * 128 + t0] = m0; g_M[bh * 128 + t1] = m1;
        g_L[bh * 128 + t0] = l0; g_L[bh * 128 + t1] = l1;
    }
}

// ---------------- attention pass 2 (fp16) -----------------------------------------
#define P2_SMEM (3 * AT_TILE + 1024)

__global__ void __launch_bounds__(256, 2)
attn2_h()
{
    extern __shared__ __align__(256) char smem[];
    const uint32_t sb = smem_u32(smem);
    float* m_s = (float*)(smem + 3 * AT_TILE);
    float* rl_s = m_s + 128;
    const int tid = threadIdx.x;
    const int wid = tid >> 5, lane = tid & 31;
    const int cc = blockIdx.x, bh = blockIdx.y, b = bh >> 4, h = bh & 15;
    const size_t row0 = (size_t)b * LVIS + cc * 128;

#pragma unroll
    for (int i = 0; i < 12; i++) {
        int q = tid + i * 256;
        int tile = q >> 10, rem = q & 1023, r = rem >> 3, s = rem & 7;
        const __half* src;
        if (tile == 0)      src = g_Q + (size_t)(b * LTEXT + r) * DD + h * HD + s * 8;
        else if (tile == 1) src = g_K + (row0 + r) * DD + h * HD + s * 8;
        else                src = g_TGV + ((size_t)bh * 128 + r) * 64 + s * 8;
        cp_async16(sb + tile * AT_TILE + r * (AT_STRIDE * 2) + s * 16, src);
    }
    CP_COMMIT();
    if (tid < 128) {
        m_s[tid] = g_M[bh * 128 + tid];
        rl_s[tid] = 1.f / g_L[bh * 128 + tid];
    }
    CP_WAIT0();
    __syncthreads();

    uint32_t kf[4][4];
#pragma unroll
    for (int ks = 0; ks < 4; ks++) {
        uint32_t off = ((wid * 16 + (lane & 15)) * AT_STRIDE + ks * 16 + (lane >> 4) * 8) * 2;
        ldsm4(kf[ks], sb + AT_TILE + off);
    }

    float S[16][4] = {};
    const int lm = lane & 7, quad = lane >> 3;
#pragma unroll
    for (int nb = 0; nb < 4; nb++) {
#pragma unroll
        for (int ks = 0; ks < 4; ks++) {
            uint32_t bq[2][4];
            const int brow = nb * 32 + ((quad & 2) ? 8 : 0) + lm;
            const int bcol = ks * 16 + (quad & 1) * 8;
#pragma unroll
            for (int np = 0; np < 2; np++)
                ldsm4(bq[np], sb + ((brow + np * 16) * AT_STRIDE + bcol) * 2);
#pragma unroll
            for (int ni = 0; ni < 4; ni++)
                mma_h(S[nb * 4 + ni], kf[ks], &bq[ni >> 1][(ni & 1) * 2]);
        }
    }

    const int q = lane & 3;
#pragma unroll
    for (int nt = 0; nt < 16; nt++) {
        int c0 = nt * 8 + q * 2;
        S[nt][0] = __expf(S[nt][0] - m_s[c0]) * rl_s[c0];
        S[nt][1] = __expf(S[nt][1] - m_s[c0 + 1]) * rl_s[c0 + 1];
        S[nt][2] = __expf(S[nt][2] - m_s[c0]) * rl_s[c0];
        S[nt][3] = __expf(S[nt][3] - m_s[c0 + 1]) * rl_s[c0 + 1];
    }

    float O[8][4] = {};
#pragma unroll
    for (int ks2 = 0; ks2 < 8; ks2++) {
        uint32_t pa[4] = {packh(S[2 * ks2][0], S[2 * ks2][1]),
                          packh(S[2 * ks2][2], S[2 * ks2][3]),
                          packh(S[2 * ks2 + 1][0], S[2 * ks2 + 1][1]),
                          packh(S[2 * ks2 + 1][2], S[2 * ks2 + 1][3])};
        const int vrow = ks2 * 16 + ((lane >> 3) & 1) * 8 + (lane & 7);
#pragma unroll
        for (int nv = 0; nv < 4; nv++) {
            const int vcol = nv * 16 + (lane >> 4) * 8;
            uint32_t bv[4];
            ldsm4t(bv, sb + 2 * AT_TILE + (vrow * AT_STRIDE + vcol) * 2);
            mma_h(O[nv * 2], pa, &bv[0]);
            mma_h(O[nv * 2 + 1], pa, &bv[2]);
        }
    }

    const int r = lane >> 2;
    const size_t s0r = row0 + wid * 16 + r;
#pragma unroll
    for (int nt = 0; nt < 8; nt++) {
        int col = h * HD + nt * 8 + q * 2;
        *(uint32_t*)&g_K[s0r * DD + col] = packh(O[nt][0], O[nt][1]);
        *(uint32_t*)&g_K[(s0r + 8) * DD + col] = packh(O[nt][2], O[nt][3]);
    }
}

// ---------------- launch ----------------------------------------------------------
extern "C" void kernel_launch(void* const* d_in, const int* in_sizes, int n_in,
                              void* d_out, int out_size)
{
    const float* hidden = nullptr;
    const float* text = nullptr;
    const float* Ws[4] = {nullptr, nullptr, nullptr, nullptr};
    const float* bs[4] = {nullptr, nullptr, nullptr, nullptr};
    int nw = 0, nb = 0;
    for (int i = 0; i < n_in; i++) {
        int sz = in_sizes[i];
        const float* p = (const float*)d_in[i];
        if (sz == BB * LVIS * DD) { if (!hidden) hidden = p; }
        else if (sz == LTEXT * BB * DD) { if (!text) text = p; }
        else if (sz == DD * DD) { if (nw < 4) Ws[nw++] = p; }
        else if (sz == DD) { if (nb < 4) bs[nb++] = p; }
    }
    if (!hidden) hidden = (const float*)d_in[0];
    if (!text) text = (const float*)d_in[1];
    if (nw < 4) { Ws[0]=(const float*)d_in[2]; Ws[1]=(const float*)d_in[4];
                  Ws[2]=(const float*)d_in[6]; Ws[3]=(const float*)d_in[8]; }
    if (nb < 4) { bs[0]=(const float*)d_in[3]; bs[1]=(const float*)d_in[5];
                  bs[2]=(const float*)d_in[7]; bs[3]=(const float*)d_in[9]; }
    float* out = (float*)d_out;

    cudaFuncSetAttribute(gemm_h, cudaFuncAttributeMaxDynamicSharedMemorySize, G_SMEM);
    cudaFuncSetAttribute(attn1_h, cudaFuncAttributeMaxDynamicSharedMemorySize, P1_SMEM);
    cudaFuncSetAttribute(attn2_h, cudaFuncAttributeMaxDynamicSharedMemorySize, P2_SMEM);

    convert_wt<<<dim3(32, 32, 4), dim3(32, 8)>>>(Ws[0], Ws[1], Ws[2], Ws[3]);
    convert_half2<<<8192, 256>>>(text, hidden);

    gemm_h<<<dim3(8, 16), 256, G_SMEM>>>(0, 0, bs[0], nullptr, 1, 0.125f);   // Q
    gemm_h<<<dim3(8, 512), 256, G_SMEM>>>(1, 1, bs[1], nullptr, 2, 1.f);     // K
    gemm_h<<<dim3(8, 512), 256, G_SMEM>>>(1, 2, bs[2], nullptr, 3, 1.f);     // V

    attn1_h<<<BB * HH, 256, P1_SMEM>>>();
    attn2_h<<<dim3(LVIS / 128, BB * HH), 256, P2_SMEM>>>();

    gemm_h<<<dim3(8, 512), 256, G_SMEM>>>(2, 3, bs[3], out, 0, 1.f);         // O
}